// round 6
// baseline (speedup 1.0000x reference)
#include <cuda_runtime.h>
#include <math_constants.h>

#define FULLMASK 0xffffffffu

// ---------------- problem constants: D=64, DY=64, K=32, TAU=1 ----------------
constexpr int TPB   = 256;
constexpr int WPB   = 8;                  // warps per block
constexpr int B1    = 592;                // 4 blocks/SM * 148 SMs, one wave
constexpr int TOTW  = B1 * WPB;           // 4736 warps
constexpr int RPI   = 8;                  // rows per warp per iter
constexpr int SWEEP = TOTW * RPI;         // 37888 rows per sweep
constexpr int C1    = B1 * 32;            // 18944 candidates
constexpr int SLICE = C1 / WPB;           // 2368 candidates per warp in final select

// ---------------- scratch ----------------
__device__ float        g_cd1[C1];
__device__ int          g_ci1[C1];
__device__ float        g_bsum[B1];
__device__ unsigned int g_ctr = 0;

// Select the 32 smallest of (sd[0..n), si[0..n)); executed by ONE warp.
// Marks selected slots +inf. Deterministic (value, then index tiebreak).
// sd/si may point to shared OR global memory.
__device__ __forceinline__ void warp_select_32(volatile float* sd, const int* si, int n,
                                               float* gD, int* gI) {
    int lane = threadIdx.x & 31;
    for (int k = 0; k < 32; k++) {
        float mv = CUDART_INF_F;
        int   mi = 0;
        for (int j = lane; j < n; j += 32) {
            float v = sd[j];
            if (v < mv) { mv = v; mi = j; }
        }
#pragma unroll
        for (int o = 16; o; o >>= 1) {
            float ov = __shfl_xor_sync(FULLMASK, mv, o);
            int   oi = __shfl_xor_sync(FULLMASK, mi, o);
            if (ov < mv || (ov == mv && oi < mi)) { mv = ov; mi = oi; }
        }
        if (lane == 0) {
            gD[k] = mv;
            gI[k] = si[mi];
            sd[mi] = CUDART_INF_F;
        }
        __syncwarp();
    }
}

__device__ __forceinline__ float dsq8(float4 a, float4 b, float4 qa, float4 qb) {
    float t, s0 = 0.f, s1 = 0.f;
    t = a.x - qa.x; s0 = fmaf(t, t, s0);
    t = a.y - qa.y; s1 = fmaf(t, t, s1);
    t = a.z - qa.z; s0 = fmaf(t, t, s0);
    t = a.w - qa.w; s1 = fmaf(t, t, s1);
    t = b.x - qb.x; s0 = fmaf(t, t, s0);
    t = b.y - qb.y; s1 = fmaf(t, t, s1);
    t = b.z - qb.z; s0 = fmaf(t, t, s0);
    t = b.w - qb.w; s1 = fmaf(t, t, s1);
    return s0 + s1;
}

// process 8 rows (rb..rb+7): distances, exp accumulation, rotated top-2 insert
__device__ __forceinline__ void process8(int rb, int it, int j, int sub,
                                         float4 a0, float4 b0v, float4 a1, float4 b1v,
                                         float4 qa, float4 qb,
                                         float& t0, float& t1, int& i0, int& i1,
                                         float& acc) {
    float s0 = dsq8(a0, b0v, qa, qb);
    float s1 = dsq8(a1, b1v, qa, qb);
#pragma unroll
    for (int o = 1; o < 8; o <<= 1) {
        s0 += __shfl_xor_sync(FULLMASK, s0, o);
        s1 += __shfl_xor_sync(FULLMASK, s1, o);
    }
    float d0 = s0 * rsqrtf(fmaxf(s0, 1e-30f));
    float d1 = s1 * rsqrtf(fmaxf(s1, 1e-30f));
    acc += __expf(-d0) + __expf(-d1);

    const int r0 = rb + sub;
    const int r1 = rb + 4 + sub;
    const int p0h = (2 * it)     & 7;   // rotate topk duty across group lanes
    const int p1h = (2 * it + 1) & 7;
    if (p0h == j && d0 < t1) {
        if (d0 < t0) { t1 = t0; i1 = i0; t0 = d0; i0 = r0; }
        else         { t1 = d0; i1 = r0; }
    }
    if (p1h == j && d1 < t1) {
        if (d1 < t0) { t1 = t0; i1 = i0; t0 = d1; i0 = r1; }
        else         { t1 = d1; i1 = r1; }
    }
}

// ---------------- fused kernel ----------------
__global__ void __launch_bounds__(256, 4) knn_fused(const float4* __restrict__ X4,
                                                    const float* __restrict__ q,
                                                    const float* __restrict__ Y,
                                                    float* __restrict__ out,
                                                    int N) {
    const int tid  = threadIdx.x;
    const int lane = tid & 31;
    const int wid  = tid >> 5;
    const int j    = lane & 7;     // position within 8-lane group
    const int sub  = lane >> 3;    // group id (0..3)
    const int gw   = blockIdx.x * WPB + wid;

    const float4 qa = *reinterpret_cast<const float4*>(q + 4 * j);
    const float4 qb = *reinterpret_cast<const float4*>(q + 32 + 4 * j);

    float t0 = CUDART_INF_F, t1 = CUDART_INF_F;  // per-lane top-2
    int   i0 = 0, i1 = 0;
    float acc = 0.f;

    if ((N & 7) == 0) {
        // fast path: every in-range iteration is fully in-bounds (rb ≡ 0 mod 8).
        // software-pipelined depth-2: next iteration's loads issued before
        // processing the current one (8 LDG.128 in flight per warp).
        int rb = gw * RPI;
        if (rb < N) {
            const float4* p = X4 + (size_t)(rb + sub) * 16;
            float4 A0 = __ldg(p + j);
            float4 B0 = __ldg(p + 8 + j);
            float4 A1 = __ldg(p + 64 + j);
            float4 B1v = __ldg(p + 72 + j);
            int it = 0;
            while (true) {
                const int  rbn  = rb + SWEEP;
                const bool more = rbn < N;
                const int  rbs  = more ? rbn : rb;        // clamped, never OOB
                const float4* pn = X4 + (size_t)(rbs + sub) * 16;
                float4 NA0 = __ldg(pn + j);
                float4 NB0 = __ldg(pn + 8 + j);
                float4 NA1 = __ldg(pn + 64 + j);
                float4 NB1 = __ldg(pn + 72 + j);

                process8(rb, it, j, sub, A0, B0, A1, B1v, qa, qb, t0, t1, i0, i1, acc);

                A0 = NA0; B0 = NB0; A1 = NA1; B1v = NB1;
                rb = rbn; ++it;
                if (!more) break;
            }
        }
    } else {
        // generic fallback (predicated)
        const float4 z4 = make_float4(0.f, 0.f, 0.f, 0.f);
        int it = 0;
        for (int rb = gw * RPI; rb < N; rb += SWEEP, ++it) {
            const int r0 = rb + sub;
            const int r1 = rb + 4 + sub;
            const bool ok0 = r0 < N;
            const bool ok1 = r1 < N;
            const float4* p0 = X4 + (size_t)r0 * 16;
            const float4* p1 = X4 + (size_t)r1 * 16;
            float4 x0a = ok0 ? __ldg(p0 + j)     : z4;
            float4 x0b = ok0 ? __ldg(p0 + 8 + j) : z4;
            float4 x1a = ok1 ? __ldg(p1 + j)     : z4;
            float4 x1b = ok1 ? __ldg(p1 + 8 + j) : z4;
            float s0 = dsq8(x0a, x0b, qa, qb);
            float s1 = dsq8(x1a, x1b, qa, qb);
#pragma unroll
            for (int o = 1; o < 8; o <<= 1) {
                s0 += __shfl_xor_sync(FULLMASK, s0, o);
                s1 += __shfl_xor_sync(FULLMASK, s1, o);
            }
            float d0 = s0 * rsqrtf(fmaxf(s0, 1e-30f));
            float d1 = s1 * rsqrtf(fmaxf(s1, 1e-30f));
            acc += ok0 ? __expf(-d0) : 0.f;
            acc += ok1 ? __expf(-d1) : 0.f;
            const int p0h = (2 * it)     & 7;
            const int p1h = (2 * it + 1) & 7;
            if (ok0 && p0h == j && d0 < t1) {
                if (d0 < t0) { t1 = t0; i1 = i0; t0 = d0; i0 = r0; }
                else         { t1 = d0; i1 = r0; }
            }
            if (ok1 && p1h == j && d1 < t1) {
                if (d1 < t0) { t1 = t0; i1 = i0; t0 = d1; i0 = r1; }
                else         { t1 = d1; i1 = r1; }
            }
        }
    }

    // ---- shared memory ----
    __shared__ float sd[2 * TPB];
    __shared__ int   si[2 * TPB];
    __shared__ float wd[WPB * 32];
    __shared__ int   wi[WPB * 32];
    __shared__ float se[WPB];
    __shared__ float fd[WPB * 32];
    __shared__ int   fi[WPB * 32];
    __shared__ float selD[32];
    __shared__ int   selI[32];
    __shared__ float selW[32];
    __shared__ float part[4][64];
    __shared__ float sredf[WPB];
    __shared__ float Ssum;
    __shared__ unsigned s_islast;

    // ---- per-block merge: 512 candidates -> 32 ----
    sd[2 * tid]     = t0;  si[2 * tid]     = i0;
    sd[2 * tid + 1] = t1;  si[2 * tid + 1] = i1;
#pragma unroll
    for (int o = 16; o; o >>= 1) acc += __shfl_xor_sync(FULLMASK, acc, o);
    if (lane == 0) se[wid] = acc;
    __syncthreads();

    // level 1: each warp top-32 of its own 64
    warp_select_32(sd + wid * 64, si + wid * 64, 64, wd + wid * 32, wi + wid * 32);
    __syncthreads();
    // level 2: warp 0 merges 256 -> 32, writes to gmem
    if (wid == 0)
        warp_select_32(wd, wi, WPB * 32, g_cd1 + blockIdx.x * 32, g_ci1 + blockIdx.x * 32);
    if (tid == 0) {
        float s = 0.f;
#pragma unroll
        for (int i = 0; i < WPB; i++) s += se[i];
        g_bsum[blockIdx.x] = s * 0.125f;   // each row counted by its 8 group lanes
    }

    // ---- last-block handoff ----
    __syncthreads();
    __threadfence();
    if (tid == 0) s_islast = (atomicAdd(&g_ctr, 1) == B1 - 1) ? 1u : 0u;
    __syncthreads();
    if (!s_islast) return;
    __threadfence();               // acquire side: order reads after counter

    // =================== FINAL REDUCTION (last block only) ===================
    if (tid == 0) g_ctr = 0;       // reset for next graph replay

    // normalizer: deterministic sum of per-block exp sums
    float ps = 0.f;
    for (int k = tid; k < B1; k += TPB) ps += g_bsum[k];
#pragma unroll
    for (int o = 16; o; o >>= 1) ps += __shfl_xor_sync(FULLMASK, ps, o);
    if (lane == 0) sredf[wid] = ps;
    __syncthreads();
    if (tid == 0) {
        float s = 0.f;
#pragma unroll
        for (int i = 0; i < WPB; i++) s += sredf[i];
        Ssum = s;
    }

    // level 1: 8 warps, each selects top-32 of its 2368-slice of the
    // (L2-resident) candidate arrays, operating directly on gmem
    warp_select_32(g_cd1 + wid * SLICE, g_ci1 + wid * SLICE, SLICE,
                   fd + wid * 32, fi + wid * 32);
    __syncthreads();
    // level 2: warp 0 merges 256 -> final 32
    if (wid == 0)
        warp_select_32(fd, fi, WPB * 32, selD, selI);
    __syncthreads();

    if (tid < 32) selW[tid] = __expf(-selD[tid]);
    __syncthreads();

    // output: 4 k-groups x 64 dims
    {
        const int dim = tid & 63;
        const int kg  = tid >> 6;
        float a = 0.f;
#pragma unroll
        for (int k = kg * 8; k < kg * 8 + 8; k++)
            a += selW[k] * __ldg(Y + (size_t)selI[k] * 64 + dim);
        part[kg][dim] = a;
    }
    __syncthreads();
    if (tid < 64)
        out[tid] = (part[0][tid] + part[1][tid] + part[2][tid] + part[3][tid]) / Ssum;
}

// ---------------- launch ----------------
extern "C" void kernel_launch(void* const* d_in, const int* in_sizes, int n_in,
                              void* d_out, int out_size) {
    const float* X = (const float*)d_in[0];   // X_train [N, 64]
    const float* Y = (const float*)d_in[1];   // y_train [N, 64]
    const float* q = (const float*)d_in[2];   // X_missing [64]
    int N = in_sizes[0] / 64;

    knn_fused<<<B1, TPB>>>((const float4*)X, q, Y, (float*)d_out, N);
}

// round 8
// speedup vs baseline: 1.1392x; 1.1392x over previous
#include <cuda_runtime.h>
#include <math_constants.h>
#include <limits.h>

#define FULLMASK 0xffffffffu

// ---------------- problem constants: D=64, DY=64, K=32, TAU=1 ----------------
constexpr int TPB   = 256;
constexpr int WPB   = 8;                  // warps per block
constexpr int B1    = 592;                // 4 blocks/SM * 148 SMs, one wave
constexpr int TOTW  = B1 * WPB;           // 4736 warps
constexpr int RPI   = 8;                  // rows per warp per iter
constexpr int SWEEP = TOTW * RPI;         // 37888 rows per sweep
constexpr int C1    = B1 * 32;            // 18944 candidates (74 * 256 exactly)
constexpr int EQBUF = 1024;

// ---------------- scratch ----------------
__device__ float        g_cd1[C1];
__device__ int          g_ci1[C1];
__device__ float        g_bsum[B1];
__device__ unsigned int g_ctr = 0;

// Select the 32 smallest of (sd[0..n), si[0..n)); ONE warp, shared memory only
// (used for the small per-block merges). Marks selected slots +inf.
__device__ __forceinline__ void warp_select_32(volatile float* sd, const int* si, int n,
                                               float* gD, int* gI) {
    int lane = threadIdx.x & 31;
    for (int k = 0; k < 32; k++) {
        float mv = CUDART_INF_F;
        int   mi = 0;
        for (int j = lane; j < n; j += 32) {
            float v = sd[j];
            if (v < mv) { mv = v; mi = j; }
        }
#pragma unroll
        for (int o = 16; o; o >>= 1) {
            float ov = __shfl_xor_sync(FULLMASK, mv, o);
            int   oi = __shfl_xor_sync(FULLMASK, mi, o);
            if (ov < mv || (ov == mv && oi < mi)) { mv = ov; mi = oi; }
        }
        if (lane == 0) {
            gD[k] = mv;
            gI[k] = si[mi];
            sd[mi] = CUDART_INF_F;
        }
        __syncwarp();
    }
}

__device__ __forceinline__ float dsq8(float4 a, float4 b, float4 qa, float4 qb) {
    float t, s0 = 0.f, s1 = 0.f;
    t = a.x - qa.x; s0 = fmaf(t, t, s0);
    t = a.y - qa.y; s1 = fmaf(t, t, s1);
    t = a.z - qa.z; s0 = fmaf(t, t, s0);
    t = a.w - qa.w; s1 = fmaf(t, t, s1);
    t = b.x - qb.x; s0 = fmaf(t, t, s0);
    t = b.y - qb.y; s1 = fmaf(t, t, s1);
    t = b.z - qb.z; s0 = fmaf(t, t, s0);
    t = b.w - qb.w; s1 = fmaf(t, t, s1);
    return s0 + s1;
}

// ---------------- fused kernel ----------------
__global__ void __launch_bounds__(256, 4) knn_fused(const float4* __restrict__ X4,
                                                    const float* __restrict__ q,
                                                    const float* __restrict__ Y,
                                                    float* __restrict__ out,
                                                    int N) {
    const int tid  = threadIdx.x;
    const int lane = tid & 31;
    const int wid  = tid >> 5;
    const int j    = lane & 7;     // position within 8-lane group
    const int sub  = lane >> 3;    // group id (0..3)
    const int gw   = blockIdx.x * WPB + wid;

    const float4 qa = *reinterpret_cast<const float4*>(q + 4 * j);
    const float4 qb = *reinterpret_cast<const float4*>(q + 32 + 4 * j);
    const float4 z4 = make_float4(0.f, 0.f, 0.f, 0.f);

    float t0 = CUDART_INF_F, t1 = CUDART_INF_F;  // per-lane top-2
    int   i0 = 0, i1 = 0;
    float acc = 0.f;

    // ---- scan (R2's proven mainloop, verbatim) ----
    int it = 0;
    for (int rb = gw * RPI; rb < N; rb += SWEEP, ++it) {
        const int r0 = rb + sub;
        const int r1 = rb + 4 + sub;
        const bool ok0 = r0 < N;
        const bool ok1 = r1 < N;
        const float4* p0 = X4 + (size_t)r0 * 16;
        const float4* p1 = X4 + (size_t)r1 * 16;
        float4 x0a = ok0 ? __ldg(p0 + j)     : z4;
        float4 x0b = ok0 ? __ldg(p0 + 8 + j) : z4;
        float4 x1a = ok1 ? __ldg(p1 + j)     : z4;
        float4 x1b = ok1 ? __ldg(p1 + 8 + j) : z4;

        float s0 = dsq8(x0a, x0b, qa, qb);
        float s1 = dsq8(x1a, x1b, qa, qb);
#pragma unroll
        for (int o = 1; o < 8; o <<= 1) {
            s0 += __shfl_xor_sync(FULLMASK, s0, o);
            s1 += __shfl_xor_sync(FULLMASK, s1, o);
        }
        float d0 = s0 * rsqrtf(fmaxf(s0, 1e-30f));
        float d1 = s1 * rsqrtf(fmaxf(s1, 1e-30f));
        acc += ok0 ? __expf(-d0) : 0.f;
        acc += ok1 ? __expf(-d1) : 0.f;

        const int p0h = (2 * it)     & 7;   // rotate topk duty across group lanes
        const int p1h = (2 * it + 1) & 7;
        if (ok0 && p0h == j && d0 < t1) {
            if (d0 < t0) { t1 = t0; i1 = i0; t0 = d0; i0 = r0; }
            else         { t1 = d0; i1 = r0; }
        }
        if (ok1 && p1h == j && d1 < t1) {
            if (d1 < t0) { t1 = t0; i1 = i0; t0 = d1; i0 = r1; }
            else         { t1 = d1; i1 = r1; }
        }
    }

    // ---- shared memory ----
    __shared__ float sd[2 * TPB];
    __shared__ int   si[2 * TPB];
    __shared__ float wd[WPB * 32];
    __shared__ int   wi[WPB * 32];
    __shared__ float se[WPB];
    __shared__ unsigned hist[256];
    __shared__ unsigned sh_bucket, sh_cumBefore;
    __shared__ int      eqbuf[EQBUF];
    __shared__ unsigned cntLess, cntEq;
    __shared__ float selD[32];
    __shared__ int   selI[32];
    __shared__ float srtD[32];
    __shared__ int   srtI[32];
    __shared__ float selW[32];
    __shared__ float part[4][64];
    __shared__ float sredf[WPB];
    __shared__ float Ssum;
    __shared__ unsigned s_islast;

    // ---- per-block merge: 512 candidates -> 32 (smem, cheap) ----
    sd[2 * tid]     = t0;  si[2 * tid]     = i0;
    sd[2 * tid + 1] = t1;  si[2 * tid + 1] = i1;
#pragma unroll
    for (int o = 16; o; o >>= 1) acc += __shfl_xor_sync(FULLMASK, acc, o);
    if (lane == 0) se[wid] = acc;
    __syncthreads();

    warp_select_32(sd + wid * 64, si + wid * 64, 64, wd + wid * 32, wi + wid * 32);
    __syncthreads();
    if (wid == 0)
        warp_select_32(wd, wi, WPB * 32, g_cd1 + blockIdx.x * 32, g_ci1 + blockIdx.x * 32);
    if (tid == 0) {
        float s = 0.f;
#pragma unroll
        for (int i = 0; i < WPB; i++) s += se[i];
        g_bsum[blockIdx.x] = s * 0.125f;   // each row counted by its 8 group lanes
    }

    // ---- last-block handoff ----
    __syncthreads();
    __threadfence();
    if (tid == 0) s_islast = (atomicAdd(&g_ctr, 1) == B1 - 1) ? 1u : 0u;
    __syncthreads();
    if (!s_islast) return;
    __threadfence();               // acquire: order candidate reads after counter

    // =================== FINAL REDUCTION (last block only) ===================
    if (tid == 0) { g_ctr = 0; cntLess = 0; cntEq = 0; }   // reset for replay

    // normalizer: deterministic sum of per-block exp sums
    float ps = 0.f;
    for (int k = tid; k < B1; k += TPB) ps += g_bsum[k];
#pragma unroll
    for (int o = 16; o; o >>= 1) ps += __shfl_xor_sync(FULLMASK, ps, o);
    if (lane == 0) sredf[wid] = ps;
    __syncthreads();
    if (tid == 0) {
        float s = 0.f;
#pragma unroll
        for (int i = 0; i < WPB; i++) s += sredf[i];
        Ssum = s;
    }

    // ---- radix select: exact uint key of the 32nd smallest distance ----
    // (positive floats are uint-monotone; C1 = 74*256 exactly -> uniform loop)
    unsigned prefix = 0, mask = 0;
    int need = 32;
    for (int p = 3; p >= 0; p--) {
        const int sh = 8 * p;
        hist[tid] = 0;
        __syncthreads();
        for (int i = tid; i < C1; i += TPB) {
            unsigned k = __float_as_uint(g_cd1[i]);
            bool ok = (k & mask) == prefix;
            unsigned b = ok ? ((k >> sh) & 0xffu) : 0xffffffffu;
            unsigned m = __match_any_sync(FULLMASK, b);
            if (ok && lane == (__ffs(m) - 1))
                atomicAdd(&hist[b], __popc(m));
        }
        __syncthreads();
        if (wid == 0) {
            unsigned loc[8], s = 0;
#pragma unroll
            for (int u = 0; u < 8; u++) { loc[u] = hist[lane * 8 + u]; s += loc[u]; }
            unsigned c = s;
#pragma unroll
            for (int o = 1; o < 32; o <<= 1) {
                unsigned v = __shfl_up_sync(FULLMASK, c, o);
                if (lane >= o) c += v;
            }
            unsigned cumBefore = c - s;   // exclusive prefix
            if (cumBefore < (unsigned)need && (unsigned)need <= cumBefore + s) {
                unsigned cb = cumBefore;
                int b = -1;
#pragma unroll
                for (int u = 0; u < 8; u++) {
                    if (b < 0) {
                        if ((unsigned)need <= cb + loc[u]) b = lane * 8 + u;
                        else cb += loc[u];
                    }
                }
                sh_bucket = (unsigned)b;
                sh_cumBefore = cb;
            }
        }
        __syncthreads();
        prefix |= sh_bucket << sh;
        mask   |= 0xffu << sh;
        need   -= (int)sh_cumBefore;
        __syncthreads();
    }
    // prefix = key of 32nd smallest; (32-need) strictly-less; need equals wanted
    const int cLess = 32 - need;

    // ---- gather winners ----
    for (int i = tid; i < C1; i += TPB) {
        unsigned k = __float_as_uint(g_cd1[i]);
        if (k < prefix) {
            unsigned s = atomicAdd(&cntLess, 1);
            selD[s] = g_cd1[i]; selI[s] = g_ci1[i];
        } else if (k == prefix) {
            unsigned s = atomicAdd(&cntEq, 1);
            if (s < EQBUF) eqbuf[s] = g_ci1[i];
        }
    }
    __syncthreads();

    // equals: take the `need` smallest indices (deterministic tiebreak)
    if (wid == 0) {
        if (cntEq <= EQBUF) {
            const int ne = (int)cntEq;
            for (int k2 = 0; k2 < need; k2++) {
                int mv = INT_MAX;
                for (int j2 = lane; j2 < ne; j2 += 32) {
                    int v = eqbuf[j2];
                    if (v < mv) mv = v;
                }
#pragma unroll
                for (int o = 16; o; o >>= 1) {
                    int ov = __shfl_xor_sync(FULLMASK, mv, o);
                    if (ov < mv) mv = ov;
                }
                if (lane == 0) {
                    selD[cLess + k2] = __uint_as_float(prefix);
                    selI[cLess + k2] = mv;
                }
                for (int j2 = lane; j2 < ne; j2 += 32)
                    if (eqbuf[j2] == mv) eqbuf[j2] = INT_MAX;
                __syncwarp();
            }
        } else {
            // pathological mass-tie fallback: scan gmem per extraction
            int last = -1;
            for (int k2 = 0; k2 < need; k2++) {
                int mv = INT_MAX;
                for (int j2 = lane; j2 < C1; j2 += 32) {
                    if (__float_as_uint(g_cd1[j2]) == prefix) {
                        int v = g_ci1[j2];
                        if (v > last && v < mv) mv = v;
                    }
                }
#pragma unroll
                for (int o = 16; o; o >>= 1) {
                    int ov = __shfl_xor_sync(FULLMASK, mv, o);
                    if (ov < mv) mv = ov;
                }
                if (lane == 0) {
                    selD[cLess + k2] = __uint_as_float(prefix);
                    selI[cLess + k2] = mv;
                }
                last = mv;
                __syncwarp();
            }
        }
    }
    __syncthreads();

    // canonical order: rank-sort the 32 pairs by (d, idx) — deterministic
    if (wid == 0) {
        float dv = selD[lane];
        int   iv = selI[lane];
        int rank = 0;
#pragma unroll
        for (int l2 = 0; l2 < 32; l2++) {
            float od = __shfl_sync(FULLMASK, dv, l2);
            int   oi = __shfl_sync(FULLMASK, iv, l2);
            if (od < dv || (od == dv && oi < iv)) rank++;
        }
        srtD[rank] = dv;
        srtI[rank] = iv;
    }
    __syncthreads();

    if (tid < 32) selW[tid] = __expf(-srtD[tid]);
    __syncthreads();

    // output: 4 k-groups x 64 dims
    {
        const int dim = tid & 63;
        const int kg  = tid >> 6;
        float a = 0.f;
#pragma unroll
        for (int k = kg * 8; k < kg * 8 + 8; k++)
            a += selW[k] * __ldg(Y + (size_t)srtI[k] * 64 + dim);
        part[kg][dim] = a;
    }
    __syncthreads();
    if (tid < 64)
        out[tid] = (part[0][tid] + part[1][tid] + part[2][tid] + part[3][tid]) / Ssum;
}

// ---------------- launch ----------------
extern "C" void kernel_launch(void* const* d_in, const int* in_sizes, int n_in,
                              void* d_out, int out_size) {
    const float* X = (const float*)d_in[0];   // X_train [N, 64]
    const float* Y = (const float*)d_in[1];   // y_train [N, 64]
    const float* q = (const float*)d_in[2];   // X_missing [64]
    int N = in_sizes[0] / 64;

    knn_fused<<<B1, TPB>>>((const float4*)X, q, Y, (float*)d_out, N);
}

// round 15
// speedup vs baseline: 1.2948x; 1.1365x over previous
#include <cuda_runtime.h>
#include <math_constants.h>
#include <limits.h>

#define FULLMASK 0xffffffffu

// ---------------- problem constants: D=64, DY=64, K=32, TAU=1 ----------------
constexpr int TPB   = 256;
constexpr int WPB   = 8;                  // warps per block
constexpr int B1    = 592;                // 4 blocks/SM * 148 SMs, one wave
constexpr int TOTW  = B1 * WPB;           // 4736 warps
constexpr int C1    = B1 * 32;            // 18944 candidates
constexpr int C4    = C1 / 4;             // 4736 float4 groups
constexpr int EQBUF = 1024;

// ---------------- scratch ----------------
__device__ float        g_cd1[C1];
__device__ int          g_ci1[C1];
__device__ float        g_bsum[B1];
__device__ unsigned int g_ctr = 0;

// Select the 32 smallest of (sd[0..n), si[0..n)); ONE warp, shared memory.
// Marks selected slots +inf. Deterministic (value, then index tiebreak).
__device__ __forceinline__ void warp_select_32(volatile float* sd, const int* si, int n,
                                               float* gD, int* gI) {
    int lane = threadIdx.x & 31;
    for (int k = 0; k < 32; k++) {
        float mv = CUDART_INF_F;
        int   mi = 0;
        for (int j = lane; j < n; j += 32) {
            float v = sd[j];
            if (v < mv) { mv = v; mi = j; }
        }
#pragma unroll
        for (int o = 16; o; o >>= 1) {
            float ov = __shfl_xor_sync(FULLMASK, mv, o);
            int   oi = __shfl_xor_sync(FULLMASK, mi, o);
            if (ov < mv || (ov == mv && oi < mi)) { mv = ov; mi = oi; }
        }
        if (lane == 0) {
            gD[k] = mv;
            gI[k] = si[mi];
            sd[mi] = CUDART_INF_F;
        }
        __syncwarp();
    }
}

__device__ __forceinline__ float dsq8(float4 a, float4 b, float4 qa, float4 qb) {
    float t, s0 = 0.f, s1 = 0.f;
    t = a.x - qa.x; s0 = fmaf(t, t, s0);
    t = a.y - qa.y; s1 = fmaf(t, t, s1);
    t = a.z - qa.z; s0 = fmaf(t, t, s0);
    t = a.w - qa.w; s1 = fmaf(t, t, s1);
    t = b.x - qb.x; s0 = fmaf(t, t, s0);
    t = b.y - qb.y; s1 = fmaf(t, t, s1);
    t = b.z - qb.z; s0 = fmaf(t, t, s0);
    t = b.w - qb.w; s1 = fmaf(t, t, s1);
    return s0 + s1;
}

// process 8 in-bounds rows (rb..rb+7) given their preloaded data
__device__ __forceinline__ void process8(int rb, int it, int j, int sub,
                                         float4 A0, float4 B0, float4 A1, float4 B1,
                                         float4 qa, float4 qb,
                                         float& t0, float& t1, int& i0, int& i1,
                                         float& acc) {
    float s0 = dsq8(A0, B0, qa, qb);
    float s1 = dsq8(A1, B1, qa, qb);
#pragma unroll
    for (int o = 1; o < 8; o <<= 1) {
        s0 += __shfl_xor_sync(FULLMASK, s0, o);
        s1 += __shfl_xor_sync(FULLMASK, s1, o);
    }
    float d0 = s0 * rsqrtf(fmaxf(s0, 1e-30f));
    float d1 = s1 * rsqrtf(fmaxf(s1, 1e-30f));
    acc += __expf(-d0) + __expf(-d1);

    const int p0h = (2 * it)     & 7;   // rotate topk duty across group lanes
    const int p1h = (2 * it + 1) & 7;
    if (p0h == j && d0 < t1) {
        const int r0 = rb + sub;
        if (d0 < t0) { t1 = t0; i1 = i0; t0 = d0; i0 = r0; }
        else         { t1 = d0; i1 = r0; }
    }
    if (p1h == j && d1 < t1) {
        const int r1 = rb + 4 + sub;
        if (d1 < t0) { t1 = t0; i1 = i0; t0 = d1; i0 = r1; }
        else         { t1 = d1; i1 = r1; }
    }
}

// ---------------- fused kernel ----------------
__global__ void __launch_bounds__(256, 4) knn_fused(const float4* __restrict__ X4,
                                                    const float* __restrict__ q,
                                                    const float* __restrict__ Y,
                                                    float* __restrict__ out,
                                                    int N) {
    const int tid  = threadIdx.x;
    const int lane = tid & 31;
    const int wid  = tid >> 5;
    const int j    = lane & 7;     // position within 8-lane group
    const int sub  = lane >> 3;    // group id (0..3)
    const int gw   = blockIdx.x * WPB + wid;

    const float4 qa = *reinterpret_cast<const float4*>(q + 4 * j);
    const float4 qb = *reinterpret_cast<const float4*>(q + 32 + 4 * j);

    float t0 = CUDART_INF_F, t1 = CUDART_INF_F;  // per-lane top-2
    int   i0 = 0, i1 = 0;
    float acc = 0.f;

    if ((N & 7) == 0) {
        // ---- contiguous-chunk scan, predicate-free steady loop ----
        // chunk is a multiple of 8, so every warp's [start,end) length is too.
        const int chunk = ((N / 8 + TOTW - 1) / TOTW) * 8;
        int rb        = gw * chunk;
        const int end = min(rb + chunk, N);
        int it = 0;
        // 16-row body: 8 independent LDG.128 issued before any math
        while (rb + 16 <= end) {
            const float4* p = X4 + (size_t)(rb + sub) * 16;
            float4 A0 = __ldg(p + j);
            float4 B0 = __ldg(p + 8 + j);
            float4 A1 = __ldg(p + 64 + j);
            float4 B1 = __ldg(p + 72 + j);
            float4 A2 = __ldg(p + 128 + j);
            float4 B2 = __ldg(p + 136 + j);
            float4 A3 = __ldg(p + 192 + j);
            float4 B3 = __ldg(p + 200 + j);
            process8(rb,     it,     j, sub, A0, B0, A1, B1, qa, qb, t0, t1, i0, i1, acc);
            process8(rb + 8, it + 1, j, sub, A2, B2, A3, B3, qa, qb, t0, t1, i0, i1, acc);
            rb += 16; it += 2;
        }
        if (rb < end) {   // one trailing 8-row group
            const float4* p = X4 + (size_t)(rb + sub) * 16;
            float4 A0 = __ldg(p + j);
            float4 B0 = __ldg(p + 8 + j);
            float4 A1 = __ldg(p + 64 + j);
            float4 B1 = __ldg(p + 72 + j);
            process8(rb, it, j, sub, A0, B0, A1, B1, qa, qb, t0, t1, i0, i1, acc);
        }
    } else {
        // generic fallback (predicated grid-stride)
        const float4 z4 = make_float4(0.f, 0.f, 0.f, 0.f);
        int it = 0;
        for (int rb = gw * 8; rb < N; rb += TOTW * 8, ++it) {
            const int r0 = rb + sub;
            const int r1 = rb + 4 + sub;
            const bool ok0 = r0 < N;
            const bool ok1 = r1 < N;
            const float4* p0 = X4 + (size_t)r0 * 16;
            const float4* p1 = X4 + (size_t)r1 * 16;
            float4 x0a = ok0 ? __ldg(p0 + j)     : z4;
            float4 x0b = ok0 ? __ldg(p0 + 8 + j) : z4;
            float4 x1a = ok1 ? __ldg(p1 + j)     : z4;
            float4 x1b = ok1 ? __ldg(p1 + 8 + j) : z4;
            float s0 = dsq8(x0a, x0b, qa, qb);
            float s1 = dsq8(x1a, x1b, qa, qb);
#pragma unroll
            for (int o = 1; o < 8; o <<= 1) {
                s0 += __shfl_xor_sync(FULLMASK, s0, o);
                s1 += __shfl_xor_sync(FULLMASK, s1, o);
            }
            float d0 = s0 * rsqrtf(fmaxf(s0, 1e-30f));
            float d1 = s1 * rsqrtf(fmaxf(s1, 1e-30f));
            acc += ok0 ? __expf(-d0) : 0.f;
            acc += ok1 ? __expf(-d1) : 0.f;
            const int p0h = (2 * it)     & 7;
            const int p1h = (2 * it + 1) & 7;
            if (ok0 && p0h == j && d0 < t1) {
                if (d0 < t0) { t1 = t0; i1 = i0; t0 = d0; i0 = r0; }
                else         { t1 = d0; i1 = r0; }
            }
            if (ok1 && p1h == j && d1 < t1) {
                if (d1 < t0) { t1 = t0; i1 = i0; t0 = d1; i0 = r1; }
                else         { t1 = d1; i1 = r1; }
            }
        }
    }

    // ---- shared memory ----
    __shared__ float sd[2 * TPB];
    __shared__ int   si[2 * TPB];
    __shared__ float wd[WPB * 32];
    __shared__ int   wi[WPB * 32];
    __shared__ float se[WPB];
    __shared__ unsigned hist[256];
    __shared__ unsigned sh_bucket, sh_cumBefore;
    __shared__ int      eqbuf[EQBUF];
    __shared__ unsigned cntLess, cntEq;
    __shared__ float selD[32];
    __shared__ int   selI[32];
    __shared__ float srtD[32];
    __shared__ int   srtI[32];
    __shared__ float selW[32];
    __shared__ float part[4][64];
    __shared__ float sredf[WPB];
    __shared__ float Ssum;
    __shared__ unsigned s_islast;

    // ---- per-block merge: 512 candidates -> 32 ----
    sd[2 * tid]     = t0;  si[2 * tid]     = i0;
    sd[2 * tid + 1] = t1;  si[2 * tid + 1] = i1;
#pragma unroll
    for (int o = 16; o; o >>= 1) acc += __shfl_xor_sync(FULLMASK, acc, o);
    if (lane == 0) se[wid] = acc;
    __syncthreads();

    warp_select_32(sd + wid * 64, si + wid * 64, 64, wd + wid * 32, wi + wid * 32);
    __syncthreads();
    if (wid == 0)
        warp_select_32(wd, wi, WPB * 32, g_cd1 + blockIdx.x * 32, g_ci1 + blockIdx.x * 32);
    if (tid == 0) {
        float s = 0.f;
#pragma unroll
        for (int i = 0; i < WPB; i++) s += se[i];
        g_bsum[blockIdx.x] = s * 0.125f;   // each row counted by its 8 group lanes
    }

    // ---- last-block handoff ----
    __syncthreads();
    __threadfence();
    if (tid == 0) s_islast = (atomicAdd(&g_ctr, 1) == B1 - 1) ? 1u : 0u;
    __syncthreads();
    if (!s_islast) return;
    __threadfence();               // acquire: order candidate reads after counter

    // =================== FINAL REDUCTION (last block only) ===================
    if (tid == 0) { g_ctr = 0; cntLess = 0; cntEq = 0; }   // reset for replay

    // normalizer: deterministic sum of per-block exp sums
    float ps = 0.f;
    for (int k = tid; k < B1; k += TPB) ps += g_bsum[k];
#pragma unroll
    for (int o = 16; o; o >>= 1) ps += __shfl_xor_sync(FULLMASK, ps, o);
    if (lane == 0) sredf[wid] = ps;
    __syncthreads();
    if (tid == 0) {
        float s = 0.f;
#pragma unroll
        for (int i = 0; i < WPB; i++) s += sredf[i];
        Ssum = s;
    }

    // ---- radix select (vectorized): exact uint key of 32nd smallest ----
    const float4* cd4 = reinterpret_cast<const float4*>(g_cd1);
    unsigned prefix = 0, mask = 0;
    int need = 32;
    for (int p = 3; p >= 0; p--) {
        const int sh = 8 * p;
        hist[tid] = 0;
        __syncthreads();
        for (int i = tid; i < C4; i += TPB) {
            float4 v = __ldg(cd4 + i);
            unsigned kk[4] = { __float_as_uint(v.x), __float_as_uint(v.y),
                               __float_as_uint(v.z), __float_as_uint(v.w) };
#pragma unroll
            for (int u = 0; u < 4; u++) {
                bool ok = (kk[u] & mask) == prefix;
                unsigned b = ok ? ((kk[u] >> sh) & 0xffu) : 0xffffffffu;
                unsigned m = __match_any_sync(FULLMASK, b);
                if (ok && lane == (__ffs(m) - 1))
                    atomicAdd(&hist[b], __popc(m));
            }
        }
        __syncthreads();
        if (wid == 0) {
            unsigned loc[8], s = 0;
#pragma unroll
            for (int u = 0; u < 8; u++) { loc[u] = hist[lane * 8 + u]; s += loc[u]; }
            unsigned c = s;
#pragma unroll
            for (int o = 1; o < 32; o <<= 1) {
                unsigned v = __shfl_up_sync(FULLMASK, c, o);
                if (lane >= o) c += v;
            }
            unsigned cumBefore = c - s;   // exclusive prefix
            if (cumBefore < (unsigned)need && (unsigned)need <= cumBefore + s) {
                unsigned cb = cumBefore;
                int b = -1;
#pragma unroll
                for (int u = 0; u < 8; u++) {
                    if (b < 0) {
                        if ((unsigned)need <= cb + loc[u]) b = lane * 8 + u;
                        else cb += loc[u];
                    }
                }
                sh_bucket = (unsigned)b;
                sh_cumBefore = cb;
            }
        }
        __syncthreads();
        prefix |= sh_bucket << sh;
        mask   |= 0xffu << sh;
        need   -= (int)sh_cumBefore;
        __syncthreads();
    }
    const int cLess = 32 - need;   // strictly-less count; `need` taken from equals

    // ---- gather winners (vectorized) ----
    for (int i = tid; i < C4; i += TPB) {
        float4 v = __ldg(cd4 + i);
        float vv[4] = { v.x, v.y, v.z, v.w };
#pragma unroll
        for (int u = 0; u < 4; u++) {
            unsigned k = __float_as_uint(vv[u]);
            if (k < prefix) {
                unsigned s = atomicAdd(&cntLess, 1);
                selD[s] = vv[u]; selI[s] = g_ci1[4 * i + u];
            } else if (k == prefix) {
                unsigned s = atomicAdd(&cntEq, 1);
                if (s < EQBUF) eqbuf[s] = g_ci1[4 * i + u];
            }
        }
    }
    __syncthreads();

    // equals: take the `need` smallest indices (deterministic tiebreak)
    if (wid == 0) {
        if (cntEq <= EQBUF) {
            const int ne = (int)cntEq;
            for (int k2 = 0; k2 < need; k2++) {
                int mv = INT_MAX;
                for (int j2 = lane; j2 < ne; j2 += 32) {
                    int v = eqbuf[j2];
                    if (v < mv) mv = v;
                }
#pragma unroll
                for (int o = 16; o; o >>= 1) {
                    int ov = __shfl_xor_sync(FULLMASK, mv, o);
                    if (ov < mv) mv = ov;
                }
                if (lane == 0) {
                    selD[cLess + k2] = __uint_as_float(prefix);
                    selI[cLess + k2] = mv;
                }
                for (int j2 = lane; j2 < ne; j2 += 32)
                    if (eqbuf[j2] == mv) eqbuf[j2] = INT_MAX;
                __syncwarp();
            }
        } else {
            // pathological mass-tie fallback: scan gmem per extraction
            int last = -1;
            for (int k2 = 0; k2 < need; k2++) {
                int mv = INT_MAX;
                for (int j2 = lane; j2 < C1; j2 += 32) {
                    if (__float_as_uint(g_cd1[j2]) == prefix) {
                        int v = g_ci1[j2];
                        if (v > last && v < mv) mv = v;
                    }
                }
#pragma unroll
                for (int o = 16; o; o >>= 1) {
                    int ov = __shfl_xor_sync(FULLMASK, mv, o);
                    if (ov < mv) mv = ov;
                }
                if (lane == 0) {
                    selD[cLess + k2] = __uint_as_float(prefix);
                    selI[cLess + k2] = mv;
                }
                last = mv;
                __syncwarp();
            }
        }
    }
    __syncthreads();

    // canonical order: rank-sort the 32 pairs by (d, idx) — deterministic
    if (wid == 0) {
        float dv = selD[lane];
        int   iv = selI[lane];
        int rank = 0;
#pragma unroll
        for (int l2 = 0; l2 < 32; l2++) {
            float od = __shfl_sync(FULLMASK, dv, l2);
            int   oi = __shfl_sync(FULLMASK, iv, l2);
            if (od < dv || (od == dv && oi < iv)) rank++;
        }
        srtD[rank] = dv;
        srtI[rank] = iv;
    }
    __syncthreads();

    if (tid < 32) selW[tid] = __expf(-srtD[tid]);
    __syncthreads();

    // output: 4 k-groups x 64 dims
    {
        const int dim = tid & 63;
        const int kg  = tid >> 6;
        float a = 0.f;
#pragma unroll
        for (int k = kg * 8; k < kg * 8 + 8; k++)
            a += selW[k] * __ldg(Y + (size_t)srtI[k] * 64 + dim);
        part[kg][dim] = a;
    }
    __syncthreads();
    if (tid < 64)
        out[tid] = (part[0][tid] + part[1][tid] + part[2][tid] + part[3][tid]) / Ssum;
}

// ---------------- launch ----------------
extern "C" void kernel_launch(void* const* d_in, const int* in_sizes, int n_in,
                              void* d_out, int out_size) {
    const float* X = (const float*)d_in[0];   // X_train [N, 64]
    const float* Y = (const float*)d_in[1];   // y_train [N, 64]
    const float* q = (const float*)d_in[2];   // X_missing [64]
    int N = in_sizes[0] / 64;

    knn_fused<<<B1, TPB>>>((const float4*)X, q, Y, (float*)d_out, N);
}

// round 16
// speedup vs baseline: 1.4556x; 1.1242x over previous
#include <cuda_runtime.h>
#include <math_constants.h>
#include <limits.h>

#define FULLMASK 0xffffffffu

// ---------------- problem constants: D=64, DY=64, K=32, TAU=1 ----------------
constexpr int TPB   = 256;
constexpr int WPB   = 8;                  // warps per block
constexpr int B1    = 592;                // 4 blocks/SM * 148 SMs, one wave
constexpr int TOTW  = B1 * WPB;           // 4736 warps
constexpr int C1    = B1 * 32;            // 18944 candidates
constexpr int C4    = C1 / 4;             // 4736 float4 groups
constexpr int KPT   = 76;                 // keys per thread in select (19 float4)
constexpr int EQBUF = 1024;

// ---------------- scratch ----------------
__device__ float g_cd1[C1];
__device__ int   g_ci1[C1];
__device__ float g_bsum[B1];

// Select the 32 smallest of (sd[0..n), si[0..n)); ONE warp, shared memory.
// Marks selected slots +inf. Deterministic (value, then index tiebreak).
__device__ __forceinline__ void warp_select_32(volatile float* sd, const int* si, int n,
                                               float* gD, int* gI) {
    int lane = threadIdx.x & 31;
    for (int k = 0; k < 32; k++) {
        float mv = CUDART_INF_F;
        int   mi = 0;
        for (int j = lane; j < n; j += 32) {
            float v = sd[j];
            if (v < mv) { mv = v; mi = j; }
        }
#pragma unroll
        for (int o = 16; o; o >>= 1) {
            float ov = __shfl_xor_sync(FULLMASK, mv, o);
            int   oi = __shfl_xor_sync(FULLMASK, mi, o);
            if (ov < mv || (ov == mv && oi < mi)) { mv = ov; mi = oi; }
        }
        if (lane == 0) {
            gD[k] = mv;
            gI[k] = si[mi];
            sd[mi] = CUDART_INF_F;
        }
        __syncwarp();
    }
}

__device__ __forceinline__ float dsq8(float4 a, float4 b, float4 qa, float4 qb) {
    float t, s0 = 0.f, s1 = 0.f;
    t = a.x - qa.x; s0 = fmaf(t, t, s0);
    t = a.y - qa.y; s1 = fmaf(t, t, s1);
    t = a.z - qa.z; s0 = fmaf(t, t, s0);
    t = a.w - qa.w; s1 = fmaf(t, t, s1);
    t = b.x - qb.x; s0 = fmaf(t, t, s0);
    t = b.y - qb.y; s1 = fmaf(t, t, s1);
    t = b.z - qb.z; s0 = fmaf(t, t, s0);
    t = b.w - qb.w; s1 = fmaf(t, t, s1);
    return s0 + s1;
}

// process 8 in-bounds rows (rb..rb+7) given their preloaded data
__device__ __forceinline__ void process8(int rb, int it, int j, int sub,
                                         float4 A0, float4 B0, float4 A1, float4 B1,
                                         float4 qa, float4 qb,
                                         float& t0, float& t1, int& i0, int& i1,
                                         float& acc) {
    float s0 = dsq8(A0, B0, qa, qb);
    float s1 = dsq8(A1, B1, qa, qb);
#pragma unroll
    for (int o = 1; o < 8; o <<= 1) {
        s0 += __shfl_xor_sync(FULLMASK, s0, o);
        s1 += __shfl_xor_sync(FULLMASK, s1, o);
    }
    float d0 = s0 * rsqrtf(fmaxf(s0, 1e-30f));
    float d1 = s1 * rsqrtf(fmaxf(s1, 1e-30f));
    acc += __expf(-d0) + __expf(-d1);

    const int p0h = (2 * it)     & 7;   // rotate topk duty across group lanes
    const int p1h = (2 * it + 1) & 7;
    if (p0h == j && d0 < t1) {
        const int r0 = rb + sub;
        if (d0 < t0) { t1 = t0; i1 = i0; t0 = d0; i0 = r0; }
        else         { t1 = d0; i1 = r0; }
    }
    if (p1h == j && d1 < t1) {
        const int r1 = rb + 4 + sub;
        if (d1 < t0) { t1 = t0; i1 = i0; t0 = d1; i0 = r1; }
        else         { t1 = d1; i1 = r1; }
    }
}

// ================= kernel A: scan + per-block top-32 =================
__global__ void __launch_bounds__(256, 4) knn_scan(const float4* __restrict__ X4,
                                                   const float* __restrict__ q,
                                                   int N) {
    const int tid  = threadIdx.x;
    const int lane = tid & 31;
    const int wid  = tid >> 5;
    const int j    = lane & 7;
    const int sub  = lane >> 3;
    const int gw   = blockIdx.x * WPB + wid;

    const float4 qa = *reinterpret_cast<const float4*>(q + 4 * j);
    const float4 qb = *reinterpret_cast<const float4*>(q + 32 + 4 * j);

    float t0 = CUDART_INF_F, t1 = CUDART_INF_F;
    int   i0 = 0, i1 = 0;
    float acc = 0.f;

    if ((N & 7) == 0) {
        // contiguous-chunk scan, predicate-free steady loop
        const int chunk = ((N / 8 + TOTW - 1) / TOTW) * 8;
        int rb        = gw * chunk;
        const int end = min(rb + chunk, N);
        int it = 0;
        while (rb + 16 <= end) {
            const float4* p = X4 + (size_t)(rb + sub) * 16;
            float4 A0 = __ldg(p + j);
            float4 B0 = __ldg(p + 8 + j);
            float4 A1 = __ldg(p + 64 + j);
            float4 B1 = __ldg(p + 72 + j);
            float4 A2 = __ldg(p + 128 + j);
            float4 B2 = __ldg(p + 136 + j);
            float4 A3 = __ldg(p + 192 + j);
            float4 B3 = __ldg(p + 200 + j);
            process8(rb,     it,     j, sub, A0, B0, A1, B1, qa, qb, t0, t1, i0, i1, acc);
            process8(rb + 8, it + 1, j, sub, A2, B2, A3, B3, qa, qb, t0, t1, i0, i1, acc);
            rb += 16; it += 2;
        }
        if (rb < end) {
            const float4* p = X4 + (size_t)(rb + sub) * 16;
            float4 A0 = __ldg(p + j);
            float4 B0 = __ldg(p + 8 + j);
            float4 A1 = __ldg(p + 64 + j);
            float4 B1 = __ldg(p + 72 + j);
            process8(rb, it, j, sub, A0, B0, A1, B1, qa, qb, t0, t1, i0, i1, acc);
        }
    } else {
        // generic fallback (predicated grid-stride)
        const float4 z4 = make_float4(0.f, 0.f, 0.f, 0.f);
        int it = 0;
        for (int rb = gw * 8; rb < N; rb += TOTW * 8, ++it) {
            const int r0 = rb + sub;
            const int r1 = rb + 4 + sub;
            const bool ok0 = r0 < N;
            const bool ok1 = r1 < N;
            const float4* p0 = X4 + (size_t)r0 * 16;
            const float4* p1 = X4 + (size_t)r1 * 16;
            float4 x0a = ok0 ? __ldg(p0 + j)     : z4;
            float4 x0b = ok0 ? __ldg(p0 + 8 + j) : z4;
            float4 x1a = ok1 ? __ldg(p1 + j)     : z4;
            float4 x1b = ok1 ? __ldg(p1 + 8 + j) : z4;
            float s0 = dsq8(x0a, x0b, qa, qb);
            float s1 = dsq8(x1a, x1b, qa, qb);
#pragma unroll
            for (int o = 1; o < 8; o <<= 1) {
                s0 += __shfl_xor_sync(FULLMASK, s0, o);
                s1 += __shfl_xor_sync(FULLMASK, s1, o);
            }
            float d0 = s0 * rsqrtf(fmaxf(s0, 1e-30f));
            float d1 = s1 * rsqrtf(fmaxf(s1, 1e-30f));
            acc += ok0 ? __expf(-d0) : 0.f;
            acc += ok1 ? __expf(-d1) : 0.f;
            const int p0h = (2 * it)     & 7;
            const int p1h = (2 * it + 1) & 7;
            if (ok0 && p0h == j && d0 < t1) {
                if (d0 < t0) { t1 = t0; i1 = i0; t0 = d0; i0 = r0; }
                else         { t1 = d0; i1 = r0; }
            }
            if (ok1 && p1h == j && d1 < t1) {
                if (d1 < t0) { t1 = t0; i1 = i0; t0 = d1; i0 = r1; }
                else         { t1 = d1; i1 = r1; }
            }
        }
    }

    __shared__ float sd[2 * TPB];
    __shared__ int   si[2 * TPB];
    __shared__ float wd[WPB * 32];
    __shared__ int   wi[WPB * 32];
    __shared__ float se[WPB];

    sd[2 * tid]     = t0;  si[2 * tid]     = i0;
    sd[2 * tid + 1] = t1;  si[2 * tid + 1] = i1;
#pragma unroll
    for (int o = 16; o; o >>= 1) acc += __shfl_xor_sync(FULLMASK, acc, o);
    if (lane == 0) se[wid] = acc;
    __syncthreads();

    warp_select_32(sd + wid * 64, si + wid * 64, 64, wd + wid * 32, wi + wid * 32);
    __syncthreads();
    if (wid == 0)
        warp_select_32(wd, wi, WPB * 32, g_cd1 + blockIdx.x * 32, g_ci1 + blockIdx.x * 32);
    if (tid == 0) {
        float s = 0.f;
#pragma unroll
        for (int i = 0; i < WPB; i++) s += se[i];
        g_bsum[blockIdx.x] = s * 0.125f;
    }
}

// ================= kernel B: register-resident radix select + output =================
__global__ void __launch_bounds__(256) knn_select(const float* __restrict__ Y,
                                                  float* __restrict__ out) {
    const int tid  = threadIdx.x;
    const int lane = tid & 31;
    const int wid  = tid >> 5;

    __shared__ unsigned hist[256];
    __shared__ unsigned sh_bucket, sh_cumBefore;
    __shared__ int      eqbuf[EQBUF];
    __shared__ unsigned cntLess, cntEq;
    __shared__ float selD[32];
    __shared__ int   selI[32];
    __shared__ float srtD[32];
    __shared__ int   srtI[32];
    __shared__ float selW[32];
    __shared__ float part[4][64];
    __shared__ float sredf[WPB];
    __shared__ float Ssum;

    if (tid == 0) { cntLess = 0; cntEq = 0; }

    // ---- load ALL candidate keys into registers (19 independent LDG.128) ----
    const float4* cd4 = reinterpret_cast<const float4*>(g_cd1);
    const float4 inf4 = make_float4(CUDART_INF_F, CUDART_INF_F, CUDART_INF_F, CUDART_INF_F);
    unsigned key[KPT];
#pragma unroll
    for (int k = 0; k < 19; k++) {
        int idx = tid + k * 256;
        float4 v = (idx < C4) ? __ldg(cd4 + idx) : inf4;
        key[4 * k + 0] = __float_as_uint(v.x);
        key[4 * k + 1] = __float_as_uint(v.y);
        key[4 * k + 2] = __float_as_uint(v.z);
        key[4 * k + 3] = __float_as_uint(v.w);
    }

    // ---- normalizer: deterministic sum of per-block exp sums ----
    float ps = 0.f;
    for (int k = tid; k < B1; k += 256) ps += g_bsum[k];
#pragma unroll
    for (int o = 16; o; o >>= 1) ps += __shfl_xor_sync(FULLMASK, ps, o);
    if (lane == 0) sredf[wid] = ps;
    __syncthreads();
    if (tid == 0) {
        float s = 0.f;
#pragma unroll
        for (int i = 0; i < WPB; i++) s += sredf[i];
        Ssum = s;
    }

    // ---- 4-pass radix select from registers ----
    unsigned prefix = 0, mask = 0;
    int need = 32;
    for (int p = 3; p >= 0; p--) {
        const int sh = 8 * p;
        hist[tid] = 0;
        __syncthreads();
#pragma unroll
        for (int k = 0; k < KPT; k++) {
            bool ok = (key[k] & mask) == prefix;
            unsigned bal = __ballot_sync(FULLMASK, ok);
            if (bal) {   // warp-uniform skip of dead groups
                unsigned b = ok ? ((key[k] >> sh) & 0xffu) : 0xffffffffu;
                unsigned m = __match_any_sync(FULLMASK, b);
                if (ok && lane == (__ffs(m) - 1))
                    atomicAdd(&hist[b], __popc(m));
            }
        }
        __syncthreads();
        if (wid == 0) {
            unsigned loc[8], s = 0;
#pragma unroll
            for (int u = 0; u < 8; u++) { loc[u] = hist[lane * 8 + u]; s += loc[u]; }
            unsigned c = s;
#pragma unroll
            for (int o = 1; o < 32; o <<= 1) {
                unsigned v = __shfl_up_sync(FULLMASK, c, o);
                if (lane >= o) c += v;
            }
            unsigned cumBefore = c - s;
            if (cumBefore < (unsigned)need && (unsigned)need <= cumBefore + s) {
                unsigned cb = cumBefore;
                int b = -1;
#pragma unroll
                for (int u = 0; u < 8; u++) {
                    if (b < 0) {
                        if ((unsigned)need <= cb + loc[u]) b = lane * 8 + u;
                        else cb += loc[u];
                    }
                }
                sh_bucket = (unsigned)b;
                sh_cumBefore = cb;
            }
        }
        __syncthreads();
        prefix |= sh_bucket << sh;
        mask   |= 0xffu << sh;
        need   -= (int)sh_cumBefore;
        __syncthreads();
    }
    const int cLess = 32 - need;

    // ---- gather winners from registers ----
#pragma unroll
    for (int k = 0; k < KPT; k++) {
        bool lt = key[k] < prefix;
        bool eq = key[k] == prefix;
        unsigned bal = __ballot_sync(FULLMASK, lt || eq);
        if (bal) {
            int gidx = 4 * (tid + (k >> 2) * 256) + (k & 3);   // element index in g_cd1
            if (lt) {
                unsigned s = atomicAdd(&cntLess, 1);
                selD[s] = __uint_as_float(key[k]); selI[s] = g_ci1[gidx];
            } else if (eq) {
                unsigned s = atomicAdd(&cntEq, 1);
                if (s < EQBUF) eqbuf[s] = g_ci1[gidx];
            }
        }
    }
    __syncthreads();

    // equals: take the `need` smallest indices (deterministic tiebreak)
    if (wid == 0) {
        if (cntEq <= EQBUF) {
            const int ne = (int)cntEq;
            for (int k2 = 0; k2 < need; k2++) {
                int mv = INT_MAX;
                for (int j2 = lane; j2 < ne; j2 += 32) {
                    int v = eqbuf[j2];
                    if (v < mv) mv = v;
                }
#pragma unroll
                for (int o = 16; o; o >>= 1) {
                    int ov = __shfl_xor_sync(FULLMASK, mv, o);
                    if (ov < mv) mv = ov;
                }
                if (lane == 0) {
                    selD[cLess + k2] = __uint_as_float(prefix);
                    selI[cLess + k2] = mv;
                }
                for (int j2 = lane; j2 < ne; j2 += 32)
                    if (eqbuf[j2] == mv) eqbuf[j2] = INT_MAX;
                __syncwarp();
            }
        } else {
            // pathological mass-tie fallback: scan gmem per extraction
            int last = -1;
            for (int k2 = 0; k2 < need; k2++) {
                int mv = INT_MAX;
                for (int j2 = lane; j2 < C1; j2 += 32) {
                    if (__float_as_uint(g_cd1[j2]) == prefix) {
                        int v = g_ci1[j2];
                        if (v > last && v < mv) mv = v;
                    }
                }
#pragma unroll
                for (int o = 16; o; o >>= 1) {
                    int ov = __shfl_xor_sync(FULLMASK, mv, o);
                    if (ov < mv) mv = ov;
                }
                if (lane == 0) {
                    selD[cLess + k2] = __uint_as_float(prefix);
                    selI[cLess + k2] = mv;
                }
                last = mv;
                __syncwarp();
            }
        }
    }
    __syncthreads();

    // canonical order: rank-sort the 32 pairs by (d, idx) — deterministic
    if (wid == 0) {
        float dv = selD[lane];
        int   iv = selI[lane];
        int rank = 0;
#pragma unroll
        for (int l2 = 0; l2 < 32; l2++) {
            float od = __shfl_sync(FULLMASK, dv, l2);
            int   oi = __shfl_sync(FULLMASK, iv, l2);
            if (od < dv || (od == dv && oi < iv)) rank++;
        }
        srtD[rank] = dv;
        srtI[rank] = iv;
    }
    __syncthreads();

    if (tid < 32) selW[tid] = __expf(-srtD[tid]);
    __syncthreads();

    // output: 4 k-groups x 64 dims
    {
        const int dim = tid & 63;
        const int kg  = tid >> 6;
        float a = 0.f;
#pragma unroll
        for (int k = kg * 8; k < kg * 8 + 8; k++)
            a += selW[k] * __ldg(Y + (size_t)srtI[k] * 64 + dim);
        part[kg][dim] = a;
    }
    __syncthreads();
    if (tid < 64)
        out[tid] = (part[0][tid] + part[1][tid] + part[2][tid] + part[3][tid]) / Ssum;
}

// ---------------- launch ----------------
extern "C" void kernel_launch(void* const* d_in, const int* in_sizes, int n_in,
                              void* d_out, int out_size) {
    const float* X = (const float*)d_in[0];   // X_train [N, 64]
    const float* Y = (const float*)d_in[1];   // y_train [N, 64]
    const float* q = (const float*)d_in[2];   // X_missing [64]
    int N = in_sizes[0] / 64;

    knn_scan<<<B1, TPB>>>((const float4*)X, q, N);
    knn_select<<<1, TPB>>>(Y, (float*)d_out);
}